// round 1
// baseline (speedup 1.0000x reference)
#include <cuda_runtime.h>
#include <mma.h>

using namespace nvcuda;

// Problem constants: B=4, L=1024, D=1024, H=16
// q/k/v/ctx scratch: [H, B*L, D] = 16*4096*1024 = 67,108,864 floats each (256 MiB)
__device__ float g_q[67108864];
__device__ float g_k[67108864];
__device__ float g_v[67108864];
__device__ float g_ctx[67108864];

// ---------------------------------------------------------------------------
// Batched TF32 wmma GEMM.
//   BT = true : C = A @ B^T   (B stored row-major [N, K])
//   BT = false: C = A @ B     (B stored row-major [K, N])
// Batch offsets: A -> (permA ? zp : z) * sA, B -> z * sB, C -> (permC ? zp : z) * sC
// where z = h*4 + b and zp = b*16 + h  (B=4, H=16 hardcoded remap).
// All dims assumed multiples of tile sizes (true for this problem).
// ---------------------------------------------------------------------------
constexpr int BM = 128, BN = 128, BK = 32;

template <bool BT>
__global__ __launch_bounds__(256) void gemm_tf32(
    const float* __restrict__ Ag, const float* __restrict__ Bg, float* __restrict__ Cg,
    int M, int N, int K, int lda, int ldb, int ldc,
    long long sA, long long sB, long long sC, int permA, int permC)
{
    const int z  = blockIdx.z;
    const int zp = (z & 3) * 16 + (z >> 2);
    const float* A = Ag + (long long)(permA ? zp : z) * sA;
    const float* Bp = Bg + (long long)z * sB;
    float* C = Cg + (long long)(permC ? zp : z) * sC;

    __shared__ float As[BM][BK + 4];
    __shared__ float Bs[BT ? BN : BK][BT ? (BK + 4) : (BN + 4)];

    const int tid = threadIdx.x;
    const int ar = tid >> 3;            // 0..31
    const int ac = (tid & 7) << 2;      // 0..28
    const int br = tid >> 5;            // 0..7   (NN B loader)
    const int bc = (tid & 31) << 2;     // 0..124 (NN B loader)

    const int rowBase = blockIdx.y * BM;
    const int colBase = blockIdx.x * BN;

    const int warpId = tid >> 5;
    const int wRow = (warpId >> 2) * 64;  // 2 warp rows
    const int wCol = (warpId & 3) * 32;   // 4 warp cols

    wmma::fragment<wmma::accumulator, 16, 16, 8, float> acc[4][2];
#pragma unroll
    for (int i = 0; i < 4; i++)
#pragma unroll
        for (int j = 0; j < 2; j++) wmma::fill_fragment(acc[i][j], 0.0f);

    for (int kt = 0; kt < K; kt += BK) {
        // Load A tile: 128 x 32
#pragma unroll
        for (int i = 0; i < 4; i++) {
            const int r = ar + i * 32;
            const float4 v = *reinterpret_cast<const float4*>(
                &A[(long long)(rowBase + r) * lda + kt + ac]);
            *reinterpret_cast<float4*>(&As[r][ac]) = v;
        }
        if constexpr (BT) {
            // B stored [N, K]: load 128 rows (N) x 32 cols (K)
#pragma unroll
            for (int i = 0; i < 4; i++) {
                const int r = ar + i * 32;
                const float4 v = *reinterpret_cast<const float4*>(
                    &Bp[(long long)(colBase + r) * ldb + kt + ac]);
                *reinterpret_cast<float4*>(&Bs[r][ac]) = v;
            }
        } else {
            // B stored [K, N]: load 32 rows (K) x 128 cols (N)
#pragma unroll
            for (int i = 0; i < 4; i++) {
                const int r = br + i * 8;
                const float4 v = *reinterpret_cast<const float4*>(
                    &Bp[(long long)(kt + r) * ldb + colBase + bc]);
                *reinterpret_cast<float4*>(&Bs[r][bc]) = v;
            }
        }
        __syncthreads();

#pragma unroll
        for (int kk = 0; kk < BK; kk += 8) {
            wmma::fragment<wmma::matrix_a, 16, 16, 8, wmma::precision::tf32, wmma::row_major> af[4];
#pragma unroll
            for (int i = 0; i < 4; i++) {
                wmma::load_matrix_sync(af[i], &As[wRow + i * 16][kk], BK + 4);
#pragma unroll
                for (int t = 0; t < af[i].num_elements; t++)
                    af[i].x[t] = wmma::__float_to_tf32(af[i].x[t]);
            }
            if constexpr (BT) {
                wmma::fragment<wmma::matrix_b, 16, 16, 8, wmma::precision::tf32, wmma::col_major> bf[2];
#pragma unroll
                for (int j = 0; j < 2; j++) {
                    wmma::load_matrix_sync(bf[j], &Bs[wCol + j * 16][kk], BK + 4);
#pragma unroll
                    for (int t = 0; t < bf[j].num_elements; t++)
                        bf[j].x[t] = wmma::__float_to_tf32(bf[j].x[t]);
                }
#pragma unroll
                for (int i = 0; i < 4; i++)
#pragma unroll
                    for (int j = 0; j < 2; j++)
                        wmma::mma_sync(acc[i][j], af[i], bf[j], acc[i][j]);
            } else {
                wmma::fragment<wmma::matrix_b, 16, 16, 8, wmma::precision::tf32, wmma::row_major> bf[2];
#pragma unroll
                for (int j = 0; j < 2; j++) {
                    wmma::load_matrix_sync(bf[j], &Bs[kk][wCol + j * 16], BN + 4);
#pragma unroll
                    for (int t = 0; t < bf[j].num_elements; t++)
                        bf[j].x[t] = wmma::__float_to_tf32(bf[j].x[t]);
                }
#pragma unroll
                for (int i = 0; i < 4; i++)
#pragma unroll
                    for (int j = 0; j < 2; j++)
                        wmma::mma_sync(acc[i][j], af[i], bf[j], acc[i][j]);
            }
        }
        __syncthreads();
    }

#pragma unroll
    for (int i = 0; i < 4; i++)
#pragma unroll
        for (int j = 0; j < 2; j++) {
            float* cp = &C[(long long)(rowBase + wRow + i * 16) * ldc + colBase + wCol + j * 16];
            wmma::store_matrix_sync(cp, acc[i][j], ldc, wmma::mem_row_major);
        }
}

// ---------------------------------------------------------------------------
// In-place masked softmax over rows of the attention region.
// attn layout [B, H, L, L]; row index = b*H*L + h*L + l; mask is [B, L, L].
// val = logit/32 - 1e9 * mask, softmax over last axis.
// ---------------------------------------------------------------------------
__global__ __launch_bounds__(256) void softmax_kernel(
    float* __restrict__ attn, const float* __restrict__ mask)
{
    const int row = blockIdx.x;          // 0 .. B*H*L-1 = 65535
    const int b = row >> 14;             // / (H*L) = /16384
    const int l = row & 1023;
    float* p = attn + (long long)row * 1024;
    const float* mp = mask + ((long long)(b << 10) + l) * 1024;

    const int tid = threadIdx.x;
    float v[4];
    float mx = -3.4e38f;
#pragma unroll
    for (int i = 0; i < 4; i++) {
        const int c = tid + i * 256;
        v[i] = p[c] * 0.03125f - 1e9f * mp[c];
        mx = fmaxf(mx, v[i]);
    }
    __shared__ float red[8];
#pragma unroll
    for (int o = 16; o; o >>= 1) mx = fmaxf(mx, __shfl_xor_sync(0xffffffffu, mx, o));
    if ((tid & 31) == 0) red[tid >> 5] = mx;
    __syncthreads();
    mx = red[0];
#pragma unroll
    for (int w = 1; w < 8; w++) mx = fmaxf(mx, red[w]);
    __syncthreads();

    float s = 0.0f;
#pragma unroll
    for (int i = 0; i < 4; i++) {
        v[i] = expf(v[i] - mx);
        s += v[i];
    }
#pragma unroll
    for (int o = 16; o; o >>= 1) s += __shfl_xor_sync(0xffffffffu, s, o);
    if ((tid & 31) == 0) red[tid >> 5] = s;
    __syncthreads();
    s = red[0];
#pragma unroll
    for (int w = 1; w < 8; w++) s += red[w];
    const float inv = 1.0f / s;
#pragma unroll
    for (int i = 0; i < 4; i++) p[tid + i * 256] = v[i] * inv;
}

// ---------------------------------------------------------------------------
// combined[b*L+l, (c*16+h)*64+e] = ctx[(h*4+b)*L + l, c*64+e]
// (torch cat-of-views reshape). One float4 per thread; both sides coalesced.
// ---------------------------------------------------------------------------
__global__ __launch_bounds__(256) void permute_kernel(
    float* __restrict__ dst, const float* __restrict__ src)
{
    const int idx = blockIdx.x * 256 + threadIdx.x;  // float4 index, < 16,777,216
    const int r  = idx >> 12;       // row (b*L + l), 4096 float4 per 16384-wide row
    const int j  = (idx & 4095) << 2;
    const int c  = j >> 10;
    const int h  = (j >> 6) & 15;
    const int e  = j & 63;
    const int b  = r >> 10;
    const int l  = r & 1023;
    const long long soff = (((long long)(h * 4 + b) << 10 | l) << 10) + (c << 6) + e;
    const float4 v = *reinterpret_cast<const float4*>(&src[soff]);
    reinterpret_cast<float4*>(dst)[idx] = v;
}

// ---------------------------------------------------------------------------
extern "C" void kernel_launch(void* const* d_in, const int* in_sizes, int n_in,
                              void* d_out, int out_size)
{
    const float* x    = (const float*)d_in[0];  // [4, 1024, 1024]
    const float* mask = (const float*)d_in[1];  // [4, 1024, 1024]
    const float* Wq   = (const float*)d_in[2];  // [16, 1024, 1024]
    const float* Wk   = (const float*)d_in[3];
    const float* Wv   = (const float*)d_in[4];
    const float* Wo   = (const float*)d_in[5];  // [16384, 1024]
    float* out  = (float*)d_out;                 // context [4,1024,1024] first
    float* attn = out + 4LL * 1024 * 1024;       // then attn [4,16,1024,1024]

    float *q, *k, *v, *ctx;
    cudaGetSymbolAddress((void**)&q,   g_q);
    cudaGetSymbolAddress((void**)&k,   g_k);
    cudaGetSymbolAddress((void**)&v,   g_v);
    cudaGetSymbolAddress((void**)&ctx, g_ctx);

    const dim3 blk(256);
    const long long LD = 1024LL * 1024;   // L*D and L*L and D*D (all 1M)
    const long long QS = 4096LL * 1024;   // per-head q/k/v batch stride

    // 1) QKV projections: per head, [4096,1024] = x @ W_h^T
    const dim3 gqkv(1024 / BN, 4096 / BM, 16);
    gemm_tf32<true><<<gqkv, blk>>>(x, Wq, q, 4096, 1024, 1024, 1024, 1024, 1024, 0, LD, QS, 0, 0);
    gemm_tf32<true><<<gqkv, blk>>>(x, Wk, k, 4096, 1024, 1024, 1024, 1024, 1024, 0, LD, QS, 0, 0);
    gemm_tf32<true><<<gqkv, blk>>>(x, Wv, v, 4096, 1024, 1024, 1024, 1024, 1024, 0, LD, QS, 0, 0);

    // 2) logits = q @ k^T, per (h,b); write into d_out attn region at [b,h] (permC)
    const dim3 gl(1024 / BN, 1024 / BM, 64);
    gemm_tf32<true><<<gl, blk>>>(q, k, attn, 1024, 1024, 1024, 1024, 1024, 1024, LD, LD, LD, 0, 1);

    // 3) masked softmax in place (scale 1/32, mask * -1e9)
    softmax_kernel<<<65536, 256>>>(attn, mask);

    // 4) ctx = attn @ v, per (h,b); A read from [b,h]-ordered d_out (permA)
    gemm_tf32<false><<<gl, blk>>>(attn, v, ctx, 1024, 1024, 1024, 1024, 1024, 1024, LD, LD, LD, 1, 0);

    // 5) permute ctx -> combined (reuse q scratch)
    permute_kernel<<<65536, 256>>>(q, ctx);

    // 6) context = combined [4096,16384] @ Wo [16384,1024]
    const dim3 gf(1024 / BN, 4096 / BM, 1);
    gemm_tf32<false><<<gf, blk>>>(q, Wo, out, 4096, 1024, 16384, 16384, 1024, 1024, 0, 0, 0, 0, 0);
}

// round 3
// speedup vs baseline: 1.2451x; 1.2451x over previous
#include <cuda_runtime.h>
#include <cstdint>
#include <mma.h>

using namespace nvcuda;

// Problem constants: B=4, L=1024, D=1024, H=16
// q/k/v/ctx scratch: [H, B*L, D] = 67,108,864 floats each (256 MiB)
__device__ float g_q[67108864];
__device__ float g_k[67108864];
__device__ float g_v[67108864];
__device__ float g_ctx[67108864];

// ---------------------------------------------------------------------------
// Batched TF32 wmma GEMM with 3-stage cp.async pipeline.
//   BT = true : C = A @ B^T   (B stored row-major [N, K])
//   BT = false: C = A @ B     (B stored row-major [K, N])
// Batch offsets: A -> (permA ? zp : z) * sA, B -> z * sB, C -> (permC ? zp : z) * sC
// where z = h*4 + b and zp = b*16 + h  (B=4, H=16 hardcoded remap).
// All dims are multiples of tile sizes for this problem. K multiple of 32.
// ---------------------------------------------------------------------------
constexpr int BM = 128, BN = 128, BK = 32;
constexpr int STG = 3;                 // pipeline stages
constexpr int LDA_S = BK + 4;          // 36 (A / BT-B smem stride)
constexpr int LDB_S = BN + 4;          // 132 (NN-B smem stride)
// smem bytes (BT layout is the larger one)
constexpr int SMEM_BYTES = STG * (BM * LDA_S + BM * LDA_S) * 4;   // 110592

__device__ __forceinline__ void cp16(const float* smem_dst, const float* src) {
    unsigned dst = (unsigned)__cvta_generic_to_shared(smem_dst);
    asm volatile("cp.async.cg.shared.global [%0], [%1], 16;\n" :: "r"(dst), "l"(src));
}

template <bool BT>
__global__ __launch_bounds__(256) void gemm_tf32(
    const float* __restrict__ Ag, const float* __restrict__ Bg, float* __restrict__ Cg,
    int M, int N, int K, int lda, int ldb, int ldc,
    long long sA, long long sB, long long sC, int permA, int permC)
{
    const int z  = blockIdx.z;
    const int zp = (z & 3) * 16 + (z >> 2);
    const float* A  = Ag + (long long)(permA ? zp : z) * sA;
    const float* Bp = Bg + (long long)z * sB;
    float* C = Cg + (long long)(permC ? zp : z) * sC;

    extern __shared__ float smem[];
    float* Asm = smem;                        // [STG][BM][LDA_S]
    float* Bsm = smem + STG * BM * LDA_S;     // BT: [STG][BN][LDA_S]; NN: [STG][BK][LDB_S]

    const int tid = threadIdx.x;
    const int ar = tid >> 3;            // 0..31
    const int ac = (tid & 7) << 2;      // 0,4,..,28
    const int br = tid >> 5;            // 0..7   (NN B loader)
    const int bc = (tid & 31) << 2;     // 0..124 (NN B loader)

    const int rowBase = blockIdx.y * BM;
    const int colBase = blockIdx.x * BN;

    const int warpId = tid >> 5;
    const int wRow = (warpId >> 2) * 64;  // 2 warp rows
    const int wCol = (warpId & 3) * 32;   // 4 warp cols

    wmma::fragment<wmma::accumulator, 16, 16, 8, float> acc[4][2];
#pragma unroll
    for (int i = 0; i < 4; i++)
#pragma unroll
        for (int j = 0; j < 2; j++) wmma::fill_fragment(acc[i][j], 0.0f);

    const int T = K >> 5;   // number of K tiles

    // ---- tile load (cp.async) ----
    auto issue = [&](int kt) {
        const int buf = kt % STG;
        const int k0 = kt << 5;
#pragma unroll
        for (int i = 0; i < 4; i++) {
            const int r = ar + i * 32;
            cp16(&Asm[(buf * BM + r) * LDA_S + ac],
                 &A[(long long)(rowBase + r) * lda + k0 + ac]);
        }
        if constexpr (BT) {
#pragma unroll
            for (int i = 0; i < 4; i++) {
                const int r = ar + i * 32;
                cp16(&Bsm[(buf * BN + r) * LDA_S + ac],
                     &Bp[(long long)(colBase + r) * ldb + k0 + ac]);
            }
        } else {
#pragma unroll
            for (int i = 0; i < 4; i++) {
                const int r = br + i * 8;
                cp16(&Bsm[(buf * BK + r) * LDB_S + bc],
                     &Bp[(long long)(k0 + r) * ldb + colBase + bc]);
            }
        }
    };

    // prologue: prefetch STG-1 tiles
#pragma unroll
    for (int s = 0; s < STG - 1; s++) {
        issue(s);
        asm volatile("cp.async.commit_group;\n");
    }

    for (int kt = 0; kt < T; kt++) {
        __syncthreads();                       // all warps done reading buf being overwritten
        const int pf = kt + STG - 1;
        if (pf < T) issue(pf);
        asm volatile("cp.async.commit_group;\n");
        asm volatile("cp.async.wait_group %0;\n" :: "n"(STG - 1));
        __syncthreads();                       // tile kt visible to all warps

        const int buf = kt % STG;
        const float* Ab = &Asm[buf * BM * LDA_S];
        const float* Bb = BT ? &Bsm[buf * BN * LDA_S] : &Bsm[buf * BK * LDB_S];

#pragma unroll
        for (int kk = 0; kk < BK; kk += 8) {
            wmma::fragment<wmma::matrix_a, 16, 16, 8, wmma::precision::tf32, wmma::row_major> af[4];
#pragma unroll
            for (int i = 0; i < 4; i++) {
                wmma::load_matrix_sync(af[i], &Ab[(wRow + i * 16) * LDA_S + kk], LDA_S);
#pragma unroll
                for (int t = 0; t < af[i].num_elements; t++)
                    af[i].x[t] = wmma::__float_to_tf32(af[i].x[t]);
            }
            if constexpr (BT) {
                wmma::fragment<wmma::matrix_b, 16, 16, 8, wmma::precision::tf32, wmma::col_major> bf[2];
#pragma unroll
                for (int j = 0; j < 2; j++) {
                    wmma::load_matrix_sync(bf[j], &Bb[(wCol + j * 16) * LDA_S + kk], LDA_S);
#pragma unroll
                    for (int t = 0; t < bf[j].num_elements; t++)
                        bf[j].x[t] = wmma::__float_to_tf32(bf[j].x[t]);
                }
#pragma unroll
                for (int i = 0; i < 4; i++)
#pragma unroll
                    for (int j = 0; j < 2; j++)
                        wmma::mma_sync(acc[i][j], af[i], bf[j], acc[i][j]);
            } else {
                wmma::fragment<wmma::matrix_b, 16, 16, 8, wmma::precision::tf32, wmma::row_major> bf[2];
#pragma unroll
                for (int j = 0; j < 2; j++) {
                    wmma::load_matrix_sync(bf[j], &Bb[kk * LDB_S + wCol + j * 16], LDB_S);
#pragma unroll
                    for (int t = 0; t < bf[j].num_elements; t++)
                        bf[j].x[t] = wmma::__float_to_tf32(bf[j].x[t]);
                }
#pragma unroll
                for (int i = 0; i < 4; i++)
#pragma unroll
                    for (int j = 0; j < 2; j++)
                        wmma::mma_sync(acc[i][j], af[i], bf[j], acc[i][j]);
            }
        }
    }

#pragma unroll
    for (int i = 0; i < 4; i++)
#pragma unroll
        for (int j = 0; j < 2; j++) {
            float* cp = &C[(long long)(rowBase + wRow + i * 16) * ldc + colBase + wCol + j * 16];
            wmma::store_matrix_sync(cp, acc[i][j], ldc, wmma::mem_row_major);
        }
}

// ---------------------------------------------------------------------------
// In-place masked softmax over rows of the attention region.
// attn layout [B, H, L, L]; row index = b*H*L + h*L + l; mask is [B, L, L].
// val = logit/32 - 1e9 * mask, softmax over last axis.
// ---------------------------------------------------------------------------
__global__ __launch_bounds__(256) void softmax_kernel(
    float* __restrict__ attn, const float* __restrict__ mask)
{
    const int row = blockIdx.x;          // 0 .. B*H*L-1 = 65535
    const int b = row >> 14;             // / (H*L) = /16384
    const int l = row & 1023;
    float* p = attn + (long long)row * 1024;
    const float* mp = mask + ((long long)(b << 10) + l) * 1024;

    const int tid = threadIdx.x;
    float v[4];
    float mx = -3.4e38f;
#pragma unroll
    for (int i = 0; i < 4; i++) {
        const int c = tid + i * 256;
        v[i] = p[c] * 0.03125f - 1e9f * mp[c];
        mx = fmaxf(mx, v[i]);
    }
    __shared__ float red[8];
#pragma unroll
    for (int o = 16; o; o >>= 1) mx = fmaxf(mx, __shfl_xor_sync(0xffffffffu, mx, o));
    if ((tid & 31) == 0) red[tid >> 5] = mx;
    __syncthreads();
    mx = red[0];
#pragma unroll
    for (int w = 1; w < 8; w++) mx = fmaxf(mx, red[w]);
    __syncthreads();

    float s = 0.0f;
#pragma unroll
    for (int i = 0; i < 4; i++) {
        v[i] = expf(v[i] - mx);
        s += v[i];
    }
#pragma unroll
    for (int o = 16; o; o >>= 1) s += __shfl_xor_sync(0xffffffffu, s, o);
    if ((tid & 31) == 0) red[tid >> 5] = s;
    __syncthreads();
    s = red[0];
#pragma unroll
    for (int w = 1; w < 8; w++) s += red[w];
    const float inv = 1.0f / s;
#pragma unroll
    for (int i = 0; i < 4; i++) p[tid + i * 256] = v[i] * inv;
}

// ---------------------------------------------------------------------------
// combined[b*L+l, (c*16+h)*64+e] = ctx[(h*4+b)*L + l, c*64+e]
// (torch cat-of-views reshape). One float4 per thread; both sides coalesced.
// ---------------------------------------------------------------------------
__global__ __launch_bounds__(256) void permute_kernel(
    float* __restrict__ dst, const float* __restrict__ src)
{
    const int idx = blockIdx.x * 256 + threadIdx.x;  // float4 index, < 16,777,216
    const int r  = idx >> 12;       // row (b*L + l), 4096 float4 per 16384-wide row
    const int j  = (idx & 4095) << 2;
    const int c  = j >> 10;
    const int h  = (j >> 6) & 15;
    const int e  = j & 63;
    const int b  = r >> 10;
    const int l  = r & 1023;
    const long long soff = (((long long)(h * 4 + b) << 10 | l) << 10) + (c << 6) + e;
    const float4 v = *reinterpret_cast<const float4*>(&src[soff]);
    reinterpret_cast<float4*>(dst)[idx] = v;
}

// ---------------------------------------------------------------------------
extern "C" void kernel_launch(void* const* d_in, const int* in_sizes, int n_in,
                              void* d_out, int out_size)
{
    const float* x    = (const float*)d_in[0];  // [4, 1024, 1024]
    const float* mask = (const float*)d_in[1];  // [4, 1024, 1024]
    const float* Wq   = (const float*)d_in[2];  // [16, 1024, 1024]
    const float* Wk   = (const float*)d_in[3];
    const float* Wv   = (const float*)d_in[4];
    const float* Wo   = (const float*)d_in[5];  // [16384, 1024]
    float* out  = (float*)d_out;                 // context [4,1024,1024] first
    float* attn = out + 4LL * 1024 * 1024;       // then attn [4,16,1024,1024]

    float *q, *k, *v, *ctx;
    cudaGetSymbolAddress((void**)&q,   g_q);
    cudaGetSymbolAddress((void**)&k,   g_k);
    cudaGetSymbolAddress((void**)&v,   g_v);
    cudaGetSymbolAddress((void**)&ctx, g_ctx);

    cudaFuncSetAttribute((const void*)gemm_tf32<true>,
                         cudaFuncAttributeMaxDynamicSharedMemorySize, SMEM_BYTES);
    cudaFuncSetAttribute((const void*)gemm_tf32<false>,
                         cudaFuncAttributeMaxDynamicSharedMemorySize, SMEM_BYTES);

    const dim3 blk(256);
    const long long LD = 1024LL * 1024;   // L*D and L*L and D*D (all 1M)
    const long long QS = 4096LL * 1024;   // per-head q/k/v batch stride

    // 1) QKV projections: per head, [4096,1024] = x @ W_h^T
    const dim3 gqkv(1024 / BN, 4096 / BM, 16);
    gemm_tf32<true><<<gqkv, blk, SMEM_BYTES>>>(x, Wq, q, 4096, 1024, 1024, 1024, 1024, 1024, 0, LD, QS, 0, 0);
    gemm_tf32<true><<<gqkv, blk, SMEM_BYTES>>>(x, Wk, k, 4096, 1024, 1024, 1024, 1024, 1024, 0, LD, QS, 0, 0);
    gemm_tf32<true><<<gqkv, blk, SMEM_BYTES>>>(x, Wv, v, 4096, 1024, 1024, 1024, 1024, 1024, 0, LD, QS, 0, 0);

    // 2) logits = q @ k^T, per (h,b); write into d_out attn region at [b,h] (permC)
    const dim3 gl(1024 / BN, 1024 / BM, 64);
    gemm_tf32<true><<<gl, blk, SMEM_BYTES>>>(q, k, attn, 1024, 1024, 1024, 1024, 1024, 1024, LD, LD, LD, 0, 1);

    // 3) masked softmax in place (scale 1/32, mask * -1e9)
    softmax_kernel<<<65536, 256>>>(attn, mask);

    // 4) ctx = attn @ v, per (h,b); A read from [b,h]-ordered d_out (permA)
    gemm_tf32<false><<<gl, blk, SMEM_BYTES>>>(attn, v, ctx, 1024, 1024, 1024, 1024, 1024, 1024, LD, LD, LD, 1, 0);

    // 5) permute ctx -> combined (reuse q scratch)
    permute_kernel<<<65536, 256>>>(q, ctx);

    // 6) context = combined [4096,16384] @ Wo [16384,1024]
    const dim3 gf(1024 / BN, 4096 / BM, 1);
    gemm_tf32<false><<<gf, blk, SMEM_BYTES>>>(q, Wo, out, 4096, 1024, 16384, 16384, 1024, 1024, 0, 0, 0, 0, 0);
}

// round 4
// speedup vs baseline: 1.3804x; 1.1086x over previous
#include <cuda_runtime.h>
#include <cstdint>
#include <mma.h>

using namespace nvcuda;

// Problem constants: B=4, L=1024, D=1024, H=16
// q/k/v/ctx scratch: [H, B*L, D] = 67,108,864 floats each (256 MiB)
__device__ float g_q[67108864];
__device__ float g_k[67108864];
__device__ float g_v[67108864];

// ---------------------------------------------------------------------------
// Batched TF32 wmma GEMM with 3-stage cp.async pipeline.
//   BT = true : C = A @ B^T   (B stored row-major [N, K])
//   BT = false: C = A @ B     (B stored row-major [K, N])
// Batch offsets: A -> (permA ? zp : z) * sA, B -> z * sB
// C store modes (permC): 0 -> z * sC; 1 -> zp * sC;
//   2 -> fused cat-of-views store: combined[(b*1024+row)*16384 + ((c*16+h)*64+e)]
//        with z = h*4+b, c = col/64, e = col%64  (sC/ldc unused for addressing).
// zp = (z&3)*16 + (z>>2)  (B=4, H=16 hardcoded remap).
// All dims are multiples of tile sizes for this problem. K multiple of 32.
// ---------------------------------------------------------------------------
constexpr int BM = 128, BN = 128, BK = 32;
constexpr int STG = 3;                 // pipeline stages
constexpr int LDA_S = BK + 4;          // 36 (A / BT-B smem stride)
constexpr int LDB_S = BN + 4;          // 132 (NN-B smem stride)
constexpr int SMEM_BYTES = STG * (BM * LDA_S + BM * LDA_S) * 4;   // 110592

__device__ __forceinline__ void cp16(const float* smem_dst, const float* src) {
    unsigned dst = (unsigned)__cvta_generic_to_shared(smem_dst);
    asm volatile("cp.async.cg.shared.global [%0], [%1], 16;\n" :: "r"(dst), "l"(src));
}

template <bool BT>
__global__ __launch_bounds__(256, 2) void gemm_tf32(
    const float* __restrict__ Ag, const float* __restrict__ Bg, float* __restrict__ Cg,
    int M, int N, int K, int lda, int ldb, int ldc,
    long long sA, long long sB, long long sC, int permA, int permC)
{
    const int z  = blockIdx.z;
    const int zp = (z & 3) * 16 + (z >> 2);
    const float* A  = Ag + (long long)(permA ? zp : z) * sA;
    const float* Bp = Bg + (long long)z * sB;

    extern __shared__ float smem[];
    float* Asm = smem;                        // [STG][BM][LDA_S]
    float* Bsm = smem + STG * BM * LDA_S;     // BT: [STG][BN][LDA_S]; NN: [STG][BK][LDB_S]

    const int tid = threadIdx.x;
    const int ar = tid >> 3;            // 0..31
    const int ac = (tid & 7) << 2;      // 0,4,..,28
    const int br = tid >> 5;            // 0..7   (NN B loader)
    const int bc = (tid & 31) << 2;     // 0..124 (NN B loader)

    const int rowBase = blockIdx.y * BM;
    const int colBase = blockIdx.x * BN;

    const int warpId = tid >> 5;
    const int wRow = (warpId >> 2) * 64;  // 2 warp rows
    const int wCol = (warpId & 3) * 32;   // 4 warp cols

    wmma::fragment<wmma::accumulator, 16, 16, 8, float> acc[4][2];
#pragma unroll
    for (int i = 0; i < 4; i++)
#pragma unroll
        for (int j = 0; j < 2; j++) wmma::fill_fragment(acc[i][j], 0.0f);

    const int T = K >> 5;   // number of K tiles

    auto issue = [&](int kt) {
        const int buf = kt % STG;
        const int k0 = kt << 5;
#pragma unroll
        for (int i = 0; i < 4; i++) {
            const int r = ar + i * 32;
            cp16(&Asm[(buf * BM + r) * LDA_S + ac],
                 &A[(long long)(rowBase + r) * lda + k0 + ac]);
        }
        if constexpr (BT) {
#pragma unroll
            for (int i = 0; i < 4; i++) {
                const int r = ar + i * 32;
                cp16(&Bsm[(buf * BN + r) * LDA_S + ac],
                     &Bp[(long long)(colBase + r) * ldb + k0 + ac]);
            }
        } else {
#pragma unroll
            for (int i = 0; i < 4; i++) {
                const int r = br + i * 8;
                cp16(&Bsm[(buf * BK + r) * LDB_S + bc],
                     &Bp[(long long)(k0 + r) * ldb + colBase + bc]);
            }
        }
    };

    // prologue: prefetch STG-1 tiles
#pragma unroll
    for (int s = 0; s < STG - 1; s++) {
        issue(s);
        asm volatile("cp.async.commit_group;\n");
    }

    for (int kt = 0; kt < T; kt++) {
        __syncthreads();                       // all warps done reading buf being overwritten
        const int pf = kt + STG - 1;
        if (pf < T) issue(pf);
        asm volatile("cp.async.commit_group;\n");
        asm volatile("cp.async.wait_group %0;\n" :: "n"(STG - 1));
        __syncthreads();                       // tile kt visible to all warps

        const int buf = kt % STG;
        const float* Ab = &Asm[buf * BM * LDA_S];
        const float* Bb = BT ? &Bsm[buf * BN * LDA_S] : &Bsm[buf * BK * LDB_S];

#pragma unroll
        for (int kk = 0; kk < BK; kk += 8) {
            wmma::fragment<wmma::matrix_a, 16, 16, 8, wmma::precision::tf32, wmma::row_major> af[4];
#pragma unroll
            for (int i = 0; i < 4; i++) {
                wmma::load_matrix_sync(af[i], &Ab[(wRow + i * 16) * LDA_S + kk], LDA_S);
#pragma unroll
                for (int t = 0; t < af[i].num_elements; t++)
                    af[i].x[t] = wmma::__float_to_tf32(af[i].x[t]);
            }
            if constexpr (BT) {
                wmma::fragment<wmma::matrix_b, 16, 16, 8, wmma::precision::tf32, wmma::col_major> bf[2];
#pragma unroll
                for (int j = 0; j < 2; j++) {
                    wmma::load_matrix_sync(bf[j], &Bb[(wCol + j * 16) * LDA_S + kk], LDA_S);
#pragma unroll
                    for (int t = 0; t < bf[j].num_elements; t++)
                        bf[j].x[t] = wmma::__float_to_tf32(bf[j].x[t]);
                }
#pragma unroll
                for (int i = 0; i < 4; i++)
#pragma unroll
                    for (int j = 0; j < 2; j++)
                        wmma::mma_sync(acc[i][j], af[i], bf[j], acc[i][j]);
            } else {
                wmma::fragment<wmma::matrix_b, 16, 16, 8, wmma::precision::tf32, wmma::row_major> bf[2];
#pragma unroll
                for (int j = 0; j < 2; j++) {
                    wmma::load_matrix_sync(bf[j], &Bb[kk * LDB_S + wCol + j * 16], LDB_S);
#pragma unroll
                    for (int t = 0; t < bf[j].num_elements; t++)
                        bf[j].x[t] = wmma::__float_to_tf32(bf[j].x[t]);
                }
#pragma unroll
                for (int i = 0; i < 4; i++)
#pragma unroll
                    for (int j = 0; j < 2; j++)
                        wmma::mma_sync(acc[i][j], af[i], bf[j], acc[i][j]);
            }
        }
    }

    if (permC == 2) {
        // Fused cat-of-views store: z = h*4+b; ctx row (of head h, batch b) l,
        // col c*64+e  ->  combined[(b*1024+row)*16384 + (c*16+h)*64 + e]
        const int b = z & 3;
        const int h = z >> 2;
        float* Cb = Cg + (long long)(b << 10) * 16384;
#pragma unroll
        for (int i = 0; i < 4; i++)
#pragma unroll
            for (int j = 0; j < 2; j++) {
                const int row = rowBase + wRow + i * 16;
                const int col = colBase + wCol + j * 16;
                const int c = col >> 6;
                const int e = col & 63;
                float* cp = &Cb[(long long)row * 16384 + ((c * 16 + h) << 6) + e];
                wmma::store_matrix_sync(cp, acc[i][j], 16384, wmma::mem_row_major);
            }
    } else {
        float* C = Cg + (long long)(permC ? zp : z) * sC;
#pragma unroll
        for (int i = 0; i < 4; i++)
#pragma unroll
            for (int j = 0; j < 2; j++) {
                float* cp = &C[(long long)(rowBase + wRow + i * 16) * ldc + colBase + wCol + j * 16];
                wmma::store_matrix_sync(cp, acc[i][j], ldc, wmma::mem_row_major);
            }
    }
}

// ---------------------------------------------------------------------------
// In-place masked softmax over rows of the attention region.
// attn layout [B, H, L, L]; row index = b*H*L + h*L + l; mask is [B, L, L].
// val = logit/32 - 1e9 * mask, softmax over last axis.
// ---------------------------------------------------------------------------
__global__ __launch_bounds__(256) void softmax_kernel(
    float* __restrict__ attn, const float* __restrict__ mask)
{
    const int row = blockIdx.x;          // 0 .. B*H*L-1 = 65535
    const int b = row >> 14;             // / (H*L) = /16384
    const int l = row & 1023;
    float* p = attn + (long long)row * 1024;
    const float* mp = mask + ((long long)(b << 10) + l) * 1024;

    const int tid = threadIdx.x;
    float v[4];
    float mx = -3.4e38f;
#pragma unroll
    for (int i = 0; i < 4; i++) {
        const int c = tid + i * 256;
        v[i] = p[c] * 0.03125f - 1e9f * mp[c];
        mx = fmaxf(mx, v[i]);
    }
    __shared__ float red[8];
#pragma unroll
    for (int o = 16; o; o >>= 1) mx = fmaxf(mx, __shfl_xor_sync(0xffffffffu, mx, o));
    if ((tid & 31) == 0) red[tid >> 5] = mx;
    __syncthreads();
    mx = red[0];
#pragma unroll
    for (int w = 1; w < 8; w++) mx = fmaxf(mx, red[w]);
    __syncthreads();

    float s = 0.0f;
#pragma unroll
    for (int i = 0; i < 4; i++) {
        v[i] = expf(v[i] - mx);
        s += v[i];
    }
#pragma unroll
    for (int o = 16; o; o >>= 1) s += __shfl_xor_sync(0xffffffffu, s, o);
    if ((tid & 31) == 0) red[tid >> 5] = s;
    __syncthreads();
    s = red[0];
#pragma unroll
    for (int w = 1; w < 8; w++) s += red[w];
    const float inv = 1.0f / s;
#pragma unroll
    for (int i = 0; i < 4; i++) p[tid + i * 256] = v[i] * inv;
}

// ---------------------------------------------------------------------------
extern "C" void kernel_launch(void* const* d_in, const int* in_sizes, int n_in,
                              void* d_out, int out_size)
{
    const float* x    = (const float*)d_in[0];  // [4, 1024, 1024]
    const float* mask = (const float*)d_in[1];  // [4, 1024, 1024]
    const float* Wq   = (const float*)d_in[2];  // [16, 1024, 1024]
    const float* Wk   = (const float*)d_in[3];
    const float* Wv   = (const float*)d_in[4];
    const float* Wo   = (const float*)d_in[5];  // [16384, 1024]
    float* out  = (float*)d_out;                 // context [4,1024,1024] first
    float* attn = out + 4LL * 1024 * 1024;       // then attn [4,16,1024,1024]

    float *q, *k, *v;
    cudaGetSymbolAddress((void**)&q, g_q);
    cudaGetSymbolAddress((void**)&k, g_k);
    cudaGetSymbolAddress((void**)&v, g_v);

    cudaFuncSetAttribute((const void*)gemm_tf32<true>,
                         cudaFuncAttributeMaxDynamicSharedMemorySize, SMEM_BYTES);
    cudaFuncSetAttribute((const void*)gemm_tf32<false>,
                         cudaFuncAttributeMaxDynamicSharedMemorySize, SMEM_BYTES);

    const dim3 blk(256);
    const long long LD = 1024LL * 1024;   // L*D and L*L and D*D (all 1M)
    const long long QS = 4096LL * 1024;   // per-head q/k/v batch stride

    // 1) QKV projections: per head, [4096,1024] = x @ W_h^T
    const dim3 gqkv(1024 / BN, 4096 / BM, 16);
    gemm_tf32<true><<<gqkv, blk, SMEM_BYTES>>>(x, Wq, q, 4096, 1024, 1024, 1024, 1024, 1024, 0, LD, QS, 0, 0);
    gemm_tf32<true><<<gqkv, blk, SMEM_BYTES>>>(x, Wk, k, 4096, 1024, 1024, 1024, 1024, 1024, 0, LD, QS, 0, 0);
    gemm_tf32<true><<<gqkv, blk, SMEM_BYTES>>>(x, Wv, v, 4096, 1024, 1024, 1024, 1024, 1024, 0, LD, QS, 0, 0);

    // 2) logits = q @ k^T, per (h,b); write into d_out attn region at [b,h] (permC=1)
    const dim3 gl(1024 / BN, 1024 / BM, 64);
    gemm_tf32<true><<<gl, blk, SMEM_BYTES>>>(q, k, attn, 1024, 1024, 1024, 1024, 1024, 1024, LD, LD, LD, 0, 1);

    // 3) masked softmax in place (scale 1/32, mask * -1e9)
    softmax_kernel<<<65536, 256>>>(attn, mask);

    // 4) ctx = attn @ v with fused cat-of-views store into q (combined buffer)
    gemm_tf32<false><<<gl, blk, SMEM_BYTES>>>(attn, v, q, 1024, 1024, 1024, 1024, 1024, 16384, LD, LD, 0, 1, 2);

    // 5) context = combined [4096,16384] @ Wo [16384,1024]
    const dim3 gf(1024 / BN, 4096 / BM, 1);
    gemm_tf32<false><<<gf, blk, SMEM_BYTES>>>(q, Wo, out, 4096, 1024, 16384, 16384, 1024, 1024, 0, 0, 0, 0, 0);
}

// round 6
// speedup vs baseline: 5.9453x; 4.3071x over previous
#include <cuda_runtime.h>
#include <cstdint>
#include <cuda_fp16.h>
#include <mma.h>

using namespace nvcuda;

// Problem constants: B=4, L=1024, D=1024, H=16
// Half scratch buffers.
__device__ __half h_x[4194304];      // x [4096,1024]
__device__ __half h_wq[16777216];    // Wq [16,1024,1024]
__device__ __half h_wk[16777216];
__device__ __half h_wv[16777216];
__device__ __half h_wo[16777216];    // Wo [16384,1024]
__device__ __half h_q[67108864];     // q [16][4096][1024]
__device__ __half h_k[67108864];
__device__ __half h_v[67108864];
__device__ __half h_attn[67108864];  // attn half copy, [b*16+h][1024][1024]
__device__ __half h_comb[67108864];  // combined [4096][16384]

// ---------------------------------------------------------------------------
constexpr int BM = 128, BN = 128, BK = 64;
constexpr int STG = 3;
constexpr int LDA_S = BK + 8;            // 72 halves (A and BT-B tiles)
constexpr int LDB_S = BN + 8;            // 136 halves (NN-B tile)
constexpr int A_TILE = BM * LDA_S;       // halves
constexpr int BT_TILE = BN * LDA_S;
constexpr int NN_TILE = BK * LDB_S;
// BT stage is the larger: (A + B) halves
constexpr int STAGE_H = A_TILE + BT_TILE;           // 18432 halves
constexpr int SMEM_BYTES = STG * STAGE_H * 2;       // 110592 B

__device__ __forceinline__ void cp16(const void* smem_dst, const void* src) {
    unsigned dst = (unsigned)__cvta_generic_to_shared(smem_dst);
    asm volatile("cp.async.cg.shared.global [%0], [%1], 16;\n" :: "r"(dst), "l"(src));
}
#define CP_COMMIT() asm volatile("cp.async.commit_group;" ::: "memory")
#define CP_WAIT(n)  asm volatile("cp.async.wait_group %0;" :: "n"(n) : "memory")

__device__ __forceinline__ int zmap(int z, int mode) {
    // 0 -> 0 ; 1 -> z ; 4 -> zp = (z&3)*16 + (z>>2)
    if (mode == 0) return 0;
    if (mode == 1) return z;
    return (z & 3) * 16 + (z >> 2);
}

// ---------------------------------------------------------------------------
// fp16 wmma GEMM, fp32 accumulate. C = A @ B^T (BT) or A @ B (NN).
// CMODE: 0 -> C + z*sC (linear);  1 -> C + zp*sC (fp32 only);
//        2 -> cat-of-views half store into combined [4096,16384], z = h*4+b.
// HOUT:  half output (via smem staging) vs direct fp32 wmma store.
// ---------------------------------------------------------------------------
template <bool BT, int CMODE, bool HOUT>
__global__ __launch_bounds__(256, 2) void gemm_h(
    const __half* __restrict__ Ag, const __half* __restrict__ Bg, void* __restrict__ Cg,
    int lda, int ldb, int ldc,
    long long sA, long long sB, long long sC,
    int K, int aZ, int bZ)
{
    const int z  = blockIdx.z;
    const int zp = (z & 3) * 16 + (z >> 2);
    const __half* A  = Ag + (long long)zmap(z, aZ) * sA;
    const __half* Bp = Bg + (long long)zmap(z, bZ) * sB;

    extern __shared__ __half smem[];
    __half* Asm = smem;                       // [STG][BM][LDA_S]
    __half* Bsm = smem + STG * A_TILE;        // BT: [STG][BN][LDA_S]; NN: [STG][BK][LDB_S]

    const int tid = threadIdx.x;
    const int warpId = tid >> 5;
    const int lane = tid & 31;
    const int rowBase = blockIdx.y * BM;
    const int colBase = blockIdx.x * BN;
    const int wRow = (warpId >> 2) * 64;
    const int wCol = (warpId & 3) * 32;

    wmma::fragment<wmma::accumulator, 16, 16, 16, float> acc[4][2];
#pragma unroll
    for (int i = 0; i < 4; i++)
#pragma unroll
        for (int j = 0; j < 2; j++) wmma::fill_fragment(acc[i][j], 0.0f);

    const int T = K >> 6;

    auto issue = [&](int kt) {
        const int buf = kt % STG;
        const int k0 = kt << 6;
        // A tile: 128 rows x 64 halves = 1024 chunks of 8 halves
#pragma unroll
        for (int i = 0; i < 4; i++) {
            const int c = tid + i * 256;
            const int r = c >> 3;
            const int col = (c & 7) << 3;
            cp16(&Asm[(buf * BM + r) * LDA_S + col],
                 &A[(long long)(rowBase + r) * lda + k0 + col]);
        }
        if constexpr (BT) {
#pragma unroll
            for (int i = 0; i < 4; i++) {
                const int c = tid + i * 256;
                const int r = c >> 3;
                const int col = (c & 7) << 3;
                cp16(&Bsm[(buf * BN + r) * LDA_S + col],
                     &Bp[(long long)(colBase + r) * ldb + k0 + col]);
            }
        } else {
            // 64 rows (K) x 128 halves (N) = 1024 chunks
#pragma unroll
            for (int i = 0; i < 4; i++) {
                const int c = tid + i * 256;
                const int r = c >> 4;
                const int col = (c & 15) << 3;
                cp16(&Bsm[(buf * BK + r) * LDB_S + col],
                     &Bp[(long long)(k0 + r) * ldb + colBase + col]);
            }
        }
    };

#pragma unroll
    for (int s = 0; s < STG - 1; s++) { issue(s); CP_COMMIT(); }

    for (int kt = 0; kt < T; kt++) {
        __syncthreads();
        const int pf = kt + STG - 1;
        if (pf < T) issue(pf);
        CP_COMMIT();
        CP_WAIT(STG - 1);
        __syncthreads();

        const int buf = kt % STG;
        const __half* Ab = &Asm[buf * BM * LDA_S];
        const __half* Bb = BT ? &Bsm[buf * BN * LDA_S] : &Bsm[buf * BK * LDB_S];

#pragma unroll
        for (int kk = 0; kk < BK; kk += 16) {
            wmma::fragment<wmma::matrix_a, 16, 16, 16, __half, wmma::row_major> af[4];
#pragma unroll
            for (int i = 0; i < 4; i++)
                wmma::load_matrix_sync(af[i], &Ab[(wRow + i * 16) * LDA_S + kk], LDA_S);
            if constexpr (BT) {
                wmma::fragment<wmma::matrix_b, 16, 16, 16, __half, wmma::col_major> bf[2];
#pragma unroll
                for (int j = 0; j < 2; j++)
                    wmma::load_matrix_sync(bf[j], &Bb[(wCol + j * 16) * LDA_S + kk], LDA_S);
#pragma unroll
                for (int i = 0; i < 4; i++)
#pragma unroll
                    for (int j = 0; j < 2; j++)
                        wmma::mma_sync(acc[i][j], af[i], bf[j], acc[i][j]);
            } else {
                wmma::fragment<wmma::matrix_b, 16, 16, 16, __half, wmma::row_major> bf[2];
#pragma unroll
                for (int j = 0; j < 2; j++)
                    wmma::load_matrix_sync(bf[j], &Bb[kk * LDB_S + wCol + j * 16], LDB_S);
#pragma unroll
                for (int i = 0; i < 4; i++)
#pragma unroll
                    for (int j = 0; j < 2; j++)
                        wmma::mma_sync(acc[i][j], af[i], bf[j], acc[i][j]);
            }
        }
    }

    if constexpr (!HOUT) {
        // direct fp32 store (CMODE 0 or 1)
        float* C = (float*)Cg + (long long)(CMODE == 1 ? zp : z) * sC;
#pragma unroll
        for (int i = 0; i < 4; i++)
#pragma unroll
            for (int j = 0; j < 2; j++) {
                float* cp = &C[(long long)(rowBase + wRow + i * 16) * ldc + colBase + wCol + j * 16];
                wmma::store_matrix_sync(cp, acc[i][j], ldc, wmma::mem_row_major);
            }
    } else {
        // half store via per-warp smem staging (reuse tile smem after drain)
        __syncthreads();
        float* patch = (float*)smem + warpId * 320;     // 16 x 20
        const int pr = lane & 15;
        const int ps = (lane >> 4) << 3;
        const int b = z & 3;
        const int h = z >> 2;
#pragma unroll
        for (int i = 0; i < 4; i++)
#pragma unroll
            for (int j = 0; j < 2; j++) {
                wmma::store_matrix_sync(patch, acc[i][j], 20, wmma::mem_row_major);
                __syncwarp();
                union { uint4 u; __half2 hh[4]; } pk;
#pragma unroll
                for (int t = 0; t < 4; t++)
                    pk.hh[t] = __floats2half2_rn(patch[pr * 20 + ps + t * 2],
                                                 patch[pr * 20 + ps + t * 2 + 1]);
                const int row = rowBase + wRow + i * 16 + pr;
                const int col = colBase + wCol + j * 16;
                __half* dst;
                if constexpr (CMODE == 2) {
                    const int cc = col >> 6;
                    const int ee = col & 63;
                    dst = (__half*)Cg + ((long long)(b << 10) + row) * 16384
                        + ((cc * 16 + h) << 6) + ee + ps;
                } else {
                    dst = (__half*)Cg + (long long)z * sC + (long long)row * ldc + col + ps;
                }
                *reinterpret_cast<uint4*>(dst) = pk.u;
                __syncwarp();
            }
    }
}

// ---------------------------------------------------------------------------
// float -> half conversion
// ---------------------------------------------------------------------------
__global__ __launch_bounds__(256) void f2h_kernel(
    const float4* __restrict__ src, __half2* __restrict__ dst)
{
    const int i = blockIdx.x * 256 + threadIdx.x;
    const float4 v = src[i];
    dst[2 * i]     = __floats2half2_rn(v.x, v.y);
    dst[2 * i + 1] = __floats2half2_rn(v.z, v.w);
}

// ---------------------------------------------------------------------------
// In-place masked softmax; also emits half copy for the ctx GEMM.
// attn [B,H,L,L] fp32; mask [B,L,L]. val = logit/32 - 1e9*mask.
// ---------------------------------------------------------------------------
__global__ __launch_bounds__(256) void softmax_kernel(
    float* __restrict__ attn, __half* __restrict__ attnh, const float* __restrict__ mask)
{
    const int row = blockIdx.x;          // 0 .. 65535
    const int b = row >> 14;
    const int l = row & 1023;
    float* p = attn + (long long)row * 1024;
    __half* ph = attnh + (long long)row * 1024;
    const float* mp = mask + ((long long)(b << 10) + l) * 1024;

    const int tid = threadIdx.x;
    float v[4];
    float mx = -3.4e38f;
#pragma unroll
    for (int i = 0; i < 4; i++) {
        const int c = tid + i * 256;
        v[i] = p[c] * 0.03125f - 1e9f * mp[c];
        mx = fmaxf(mx, v[i]);
    }
    __shared__ float red[8];
#pragma unroll
    for (int o = 16; o; o >>= 1) mx = fmaxf(mx, __shfl_xor_sync(0xffffffffu, mx, o));
    if ((tid & 31) == 0) red[tid >> 5] = mx;
    __syncthreads();
    mx = red[0];
#pragma unroll
    for (int w = 1; w < 8; w++) mx = fmaxf(mx, red[w]);
    __syncthreads();

    float s = 0.0f;
#pragma unroll
    for (int i = 0; i < 4; i++) {
        v[i] = expf(v[i] - mx);
        s += v[i];
    }
#pragma unroll
    for (int o = 16; o; o >>= 1) s += __shfl_xor_sync(0xffffffffu, s, o);
    if ((tid & 31) == 0) red[tid >> 5] = s;
    __syncthreads();
    s = red[0];
#pragma unroll
    for (int w = 1; w < 8; w++) s += red[w];
    const float inv = 1.0f / s;
#pragma unroll
    for (int i = 0; i < 4; i++) {
        const int c = tid + i * 256;
        const float r = v[i] * inv;
        p[c] = r;
        ph[c] = __float2half_rn(r);
    }
}

// ---------------------------------------------------------------------------
extern "C" void kernel_launch(void* const* d_in, const int* in_sizes, int n_in,
                              void* d_out, int out_size)
{
    const float* x    = (const float*)d_in[0];
    const float* mask = (const float*)d_in[1];
    const float* Wq   = (const float*)d_in[2];
    const float* Wk   = (const float*)d_in[3];
    const float* Wv   = (const float*)d_in[4];
    const float* Wo   = (const float*)d_in[5];
    float* out  = (float*)d_out;
    float* attn = out + 4LL * 1024 * 1024;

    __half *xh, *wqh, *wkh, *wvh, *woh, *qh, *kh, *vh, *ah, *ch;
    cudaGetSymbolAddress((void**)&xh,  h_x);
    cudaGetSymbolAddress((void**)&wqh, h_wq);
    cudaGetSymbolAddress((void**)&wkh, h_wk);
    cudaGetSymbolAddress((void**)&wvh, h_wv);
    cudaGetSymbolAddress((void**)&woh, h_wo);
    cudaGetSymbolAddress((void**)&qh,  h_q);
    cudaGetSymbolAddress((void**)&kh,  h_k);
    cudaGetSymbolAddress((void**)&vh,  h_v);
    cudaGetSymbolAddress((void**)&ah,  h_attn);
    cudaGetSymbolAddress((void**)&ch,  h_comb);

    cudaFuncSetAttribute((const void*)gemm_h<true, 0, true>,
                         cudaFuncAttributeMaxDynamicSharedMemorySize, SMEM_BYTES);
    cudaFuncSetAttribute((const void*)gemm_h<true, 1, false>,
                         cudaFuncAttributeMaxDynamicSharedMemorySize, SMEM_BYTES);
    cudaFuncSetAttribute((const void*)gemm_h<false, 2, true>,
                         cudaFuncAttributeMaxDynamicSharedMemorySize, SMEM_BYTES);
    cudaFuncSetAttribute((const void*)gemm_h<false, 0, false>,
                         cudaFuncAttributeMaxDynamicSharedMemorySize, SMEM_BYTES);

    const long long M1 = 1024LL * 1024;
    const long long M4 = 4096LL * 1024;
    const dim3 blk(256);

    // 0) convert inputs to half
    f2h_kernel<<<4096, 256>>>((const float4*)x, (__half2*)xh);
    f2h_kernel<<<16384, 256>>>((const float4*)Wq, (__half2*)wqh);
    f2h_kernel<<<16384, 256>>>((const float4*)Wk, (__half2*)wkh);
    f2h_kernel<<<16384, 256>>>((const float4*)Wv, (__half2*)wvh);
    f2h_kernel<<<16384, 256>>>((const float4*)Wo, (__half2*)woh);

    // 1) q/k/v = x @ W_h^T per head (M=4096, N=1024, K=1024), half out
    const dim3 gp(8, 32, 16);
    gemm_h<true, 0, true><<<gp, blk, SMEM_BYTES>>>(xh, wqh, qh, 1024, 1024, 1024, 0, M1, M4, 1024, 0, 1);
    gemm_h<true, 0, true><<<gp, blk, SMEM_BYTES>>>(xh, wkh, kh, 1024, 1024, 1024, 0, M1, M4, 1024, 0, 1);
    gemm_h<true, 0, true><<<gp, blk, SMEM_BYTES>>>(xh, wvh, vh, 1024, 1024, 1024, 0, M1, M4, 1024, 0, 1);

    // 2) logits = q @ k^T per (h,b), z=h*4+b; fp32 store at [b,h] (CMODE=1)
    const dim3 gl(8, 8, 64);
    gemm_h<true, 1, false><<<gl, blk, SMEM_BYTES>>>(qh, kh, attn, 1024, 1024, 1024, M1, M1, M1, 1024, 1, 1);

    // 3) masked softmax in place (scale 1/32) + half copy
    softmax_kernel<<<65536, 256>>>(attn, ah, mask);

    // 4) ctx = attn @ v, fused cat-of-views half store into combined
    gemm_h<false, 2, true><<<gl, blk, SMEM_BYTES>>>(ah, vh, ch, 1024, 1024, 16384, M1, M1, 0, 1024, 4, 1);

    // 5) out = combined [4096,16384] @ Wo [16384,1024], fp32 out
    const dim3 gf(8, 32, 1);
    gemm_h<false, 0, false><<<gf, blk, SMEM_BYTES>>>(ch, woh, out, 16384, 1024, 1024, 0, 0, 0, 16384, 0, 0);
}

// round 7
// speedup vs baseline: 7.4543x; 1.2538x over previous
#include <cuda_runtime.h>
#include <cstdint>
#include <cuda_fp16.h>
#include <mma.h>

using namespace nvcuda;

// Problem constants: B=4, L=1024, D=1024, H=16
// Half scratch buffers.
__device__ __half h_x[4194304];      // x [4096,1024]
__device__ __half h_wk[16777216];    // Wk [16,1024,1024]
__device__ __half h_wqT[16777216];   // Wq^T per head [16][i][d]
__device__ __half h_wvT[16777216];   // Wv^T per head [16][e][d]
__device__ __half h_wog[16777216];   // gathered Wo: [16][d][o] = Wo[((d>>6)*16+h)*64+(d&63)][o]
__device__ __half h_G[16777216];     // G_h = Wq_h^T Wk_h  [16][1024][1024]
__device__ __half h_U[16777216];     // U_h = Wv_h^T Wo'_h [16][1024][1024]
__device__ __half h_P[67108864];     // P = x @ G  [16][4096][1024]
__device__ __half h_Y[67108864];     // Y = x_b @ U_h  [(h*4+b)][1024][1024]
__device__ __half h_attn[67108864];  // attn half copy [b*16+h][1024][1024]

// ---------------------------------------------------------------------------
constexpr int BM = 128, BN = 128, BK = 64;
constexpr int STG = 3;
constexpr int LDA_S = BK + 8;            // 72 halves
constexpr int LDB_S = BN + 8;            // 136 halves
constexpr int A_TILE = BM * LDA_S;
constexpr int BT_TILE = BN * LDA_S;
constexpr int STAGE_H = A_TILE + BT_TILE;           // 18432 halves (max of BT/NN)
constexpr int SMEM_BYTES = STG * STAGE_H * 2;       // 110592 B

__device__ __forceinline__ void cp16(const void* smem_dst, const void* src) {
    unsigned dst = (unsigned)__cvta_generic_to_shared(smem_dst);
    asm volatile("cp.async.cg.shared.global [%0], [%1], 16;\n" :: "r"(dst), "l"(src));
}
#define CP_COMMIT() asm volatile("cp.async.commit_group;" ::: "memory")
#define CP_WAIT(n)  asm volatile("cp.async.wait_group %0;" :: "n"(n) : "memory")

__device__ __forceinline__ int zmap(int z, int mode) {
    // 0 -> 0 ; 1 -> z ; 2 -> z&3 ; 3 -> z>>2 ; 4 -> zp
    switch (mode) {
        case 0: return 0;
        case 1: return z;
        case 2: return z & 3;
        case 3: return z >> 2;
        default: return (z & 3) * 16 + (z >> 2);
    }
}

// ---------------------------------------------------------------------------
// fp16 wmma GEMM, fp32 accumulate.
//   BT   : C = A @ B^T (B stored [N,K]); else C = A @ B (B stored [K,N]).
//   SEGK : segmented-K final GEMM. K index k=(h*1024+m); per K-tile:
//          A tile base = A + (k0>>10)*2^20 + (k0&1023), row stride 1024
//          B tile base = B + (k0>>10)*2^22 + (k0&1023)*1024, row stride 1024
//   CMODE: 0 -> C + z*sC;  1 -> C + zp*sC (fp32 only).
//   HOUT : half output via smem staging; else direct fp32 wmma store.
// ---------------------------------------------------------------------------
template <bool BT, bool SEGK, int CMODE, bool HOUT>
__global__ __launch_bounds__(256, 2) void gemm_h(
    const __half* __restrict__ Ag, const __half* __restrict__ Bg, void* __restrict__ Cg,
    int lda, int ldb, int ldc,
    long long sA, long long sB, long long sC,
    int K, int aZ, int bZ)
{
    const int z  = blockIdx.z;
    const int zp = (z & 3) * 16 + (z >> 2);
    const __half* A  = Ag + (long long)zmap(z, aZ) * sA;
    const __half* Bp = Bg + (long long)zmap(z, bZ) * sB;

    extern __shared__ __half smem[];
    __half* Asm = smem;
    __half* Bsm = smem + STG * A_TILE;

    const int tid = threadIdx.x;
    const int warpId = tid >> 5;
    const int lane = tid & 31;
    const int rowBase = blockIdx.y * BM;
    const int colBase = blockIdx.x * BN;
    const int wRow = (warpId >> 2) * 64;
    const int wCol = (warpId & 3) * 32;

    wmma::fragment<wmma::accumulator, 16, 16, 16, float> acc[4][2];
#pragma unroll
    for (int i = 0; i < 4; i++)
#pragma unroll
        for (int j = 0; j < 2; j++) wmma::fill_fragment(acc[i][j], 0.0f);

    const int T = K >> 6;

    auto issue = [&](int kt) {
        const int buf = kt % STG;
        const int k0 = kt << 6;
        const __half* At;
        const __half* Bt;
        int rs_a = lda, rs_b = ldb;
        if constexpr (SEGK) {
            const int hseg = k0 >> 10;
            const int m0 = k0 & 1023;
            At = A + ((long long)hseg << 20) + m0;                 // + row*1024
            Bt = Bp + ((long long)hseg << 22) + (long long)m0 * 1024;
            rs_a = 1024; rs_b = 1024;
        } else {
            At = A + k0;
            Bt = Bp + (BT ? k0 : (long long)k0 * ldb);
        }
        // A tile: 128 rows x 64 halves
#pragma unroll
        for (int i = 0; i < 4; i++) {
            const int c = tid + i * 256;
            const int r = c >> 3;
            const int col = (c & 7) << 3;
            cp16(&Asm[(buf * BM + r) * LDA_S + col],
                 &At[(long long)(rowBase + r) * rs_a + col]);
        }
        if constexpr (BT) {
#pragma unroll
            for (int i = 0; i < 4; i++) {
                const int c = tid + i * 256;
                const int r = c >> 3;
                const int col = (c & 7) << 3;
                cp16(&Bsm[(buf * BN + r) * LDA_S + col],
                     &Bt[(long long)(colBase + r) * rs_b + col]);
            }
        } else {
#pragma unroll
            for (int i = 0; i < 4; i++) {
                const int c = tid + i * 256;
                const int r = c >> 4;
                const int col = (c & 15) << 3;
                cp16(&Bsm[(buf * BK + r) * LDB_S + col],
                     &Bt[(long long)r * rs_b + colBase + col]);
            }
        }
    };

#pragma unroll
    for (int s = 0; s < STG - 1; s++) { issue(s); CP_COMMIT(); }

    for (int kt = 0; kt < T; kt++) {
        __syncthreads();
        const int pf = kt + STG - 1;
        if (pf < T) issue(pf);
        CP_COMMIT();
        CP_WAIT(STG - 1);
        __syncthreads();

        const int buf = kt % STG;
        const __half* Ab = &Asm[buf * BM * LDA_S];
        const __half* Bb = BT ? &Bsm[buf * BN * LDA_S] : &Bsm[buf * BK * LDB_S];

#pragma unroll
        for (int kk = 0; kk < BK; kk += 16) {
            wmma::fragment<wmma::matrix_a, 16, 16, 16, __half, wmma::row_major> af[4];
#pragma unroll
            for (int i = 0; i < 4; i++)
                wmma::load_matrix_sync(af[i], &Ab[(wRow + i * 16) * LDA_S + kk], LDA_S);
            if constexpr (BT) {
                wmma::fragment<wmma::matrix_b, 16, 16, 16, __half, wmma::col_major> bf[2];
#pragma unroll
                for (int j = 0; j < 2; j++)
                    wmma::load_matrix_sync(bf[j], &Bb[(wCol + j * 16) * LDA_S + kk], LDA_S);
#pragma unroll
                for (int i = 0; i < 4; i++)
#pragma unroll
                    for (int j = 0; j < 2; j++)
                        wmma::mma_sync(acc[i][j], af[i], bf[j], acc[i][j]);
            } else {
                wmma::fragment<wmma::matrix_b, 16, 16, 16, __half, wmma::row_major> bf[2];
#pragma unroll
                for (int j = 0; j < 2; j++)
                    wmma::load_matrix_sync(bf[j], &Bb[kk * LDB_S + wCol + j * 16], LDB_S);
#pragma unroll
                for (int i = 0; i < 4; i++)
#pragma unroll
                    for (int j = 0; j < 2; j++)
                        wmma::mma_sync(acc[i][j], af[i], bf[j], acc[i][j]);
            }
        }
    }

    if constexpr (!HOUT) {
        float* C = (float*)Cg + (long long)(CMODE == 1 ? zp : z) * sC;
#pragma unroll
        for (int i = 0; i < 4; i++)
#pragma unroll
            for (int j = 0; j < 2; j++) {
                float* cp = &C[(long long)(rowBase + wRow + i * 16) * ldc + colBase + wCol + j * 16];
                wmma::store_matrix_sync(cp, acc[i][j], ldc, wmma::mem_row_major);
            }
    } else {
        __syncthreads();
        float* patch = (float*)smem + warpId * 320;     // 16 x 20
        const int pr = lane & 15;
        const int ps = (lane >> 4) << 3;
#pragma unroll
        for (int i = 0; i < 4; i++)
#pragma unroll
            for (int j = 0; j < 2; j++) {
                wmma::store_matrix_sync(patch, acc[i][j], 20, wmma::mem_row_major);
                __syncwarp();
                union { uint4 u; __half2 hh[4]; } pk;
#pragma unroll
                for (int t = 0; t < 4; t++)
                    pk.hh[t] = __floats2half2_rn(patch[pr * 20 + ps + t * 2],
                                                 patch[pr * 20 + ps + t * 2 + 1]);
                const int row = rowBase + wRow + i * 16 + pr;
                const int col = colBase + wCol + j * 16;
                __half* dst = (__half*)Cg + (long long)z * sC + (long long)row * ldc + col + ps;
                *reinterpret_cast<uint4*>(dst) = pk.u;
                __syncwarp();
            }
    }
}

// ---------------------------------------------------------------------------
// float -> half conversion
// ---------------------------------------------------------------------------
__global__ __launch_bounds__(256) void f2h_kernel(
    const float4* __restrict__ src, __half2* __restrict__ dst)
{
    const int i = blockIdx.x * 256 + threadIdx.x;
    const float4 v = src[i];
    dst[2 * i]     = __floats2half2_rn(v.x, v.y);
    dst[2 * i + 1] = __floats2half2_rn(v.z, v.w);
}

// ---------------------------------------------------------------------------
// Per-head transpose + convert: dst[z][i][d] = src[z][d][i], half out.
// ---------------------------------------------------------------------------
__global__ void f2h_T(const float* __restrict__ src, __half* __restrict__ dst)
{
    __shared__ float t[32][33];
    const float* s = src + (long long)blockIdx.z * 1048576;
    __half* d = dst + (long long)blockIdx.z * 1048576;
    const int bx = blockIdx.x * 32;   // i base
    const int by = blockIdx.y * 32;   // d base
    const int tx = threadIdx.x, ty = threadIdx.y;
#pragma unroll
    for (int i = 0; i < 4; i++)
        t[ty + i * 8][tx] = s[(long long)(by + ty + i * 8) * 1024 + bx + tx];
    __syncthreads();
#pragma unroll
    for (int i = 0; i < 4; i++)
        d[(long long)(bx + ty + i * 8) * 1024 + by + tx] = __float2half_rn(t[tx][ty + i * 8]);
}

// ---------------------------------------------------------------------------
// Gather + convert Wo: wog[h][dd][o] = Wo[((dd>>6)*16+h)*64+(dd&63)][o]
// ---------------------------------------------------------------------------
__global__ __launch_bounds__(256) void f2h_gather(
    const float4* __restrict__ wo, __half2* __restrict__ dst)
{
    const int idx = blockIdx.x * 256 + threadIdx.x;   // < 16*1024*256
    const int o4 = idx & 255;
    const int dd = (idx >> 8) & 1023;
    const int h  = idx >> 18;
    const int srcRow = ((dd >> 6) * 16 + h) * 64 + (dd & 63);
    const float4 v = wo[(long long)srcRow * 256 + o4];
    dst[2 * idx]     = __floats2half2_rn(v.x, v.y);
    dst[2 * idx + 1] = __floats2half2_rn(v.z, v.w);
}

// ---------------------------------------------------------------------------
// In-place masked softmax; also emits half copy for the final GEMM.
// attn [B,H,L,L] fp32; mask [B,L,L]. val = logit/32 - 1e9*mask.
// ---------------------------------------------------------------------------
__global__ __launch_bounds__(256) void softmax_kernel(
    float* __restrict__ attn, __half* __restrict__ attnh, const float* __restrict__ mask)
{
    const int row = blockIdx.x;          // 0 .. 65535
    const int b = row >> 14;
    const int l = row & 1023;
    float* p = attn + (long long)row * 1024;
    __half* ph = attnh + (long long)row * 1024;
    const float* mp = mask + ((long long)(b << 10) + l) * 1024;

    const int tid = threadIdx.x;
    float v[4];
    float mx = -3.4e38f;
#pragma unroll
    for (int i = 0; i < 4; i++) {
        const int c = tid + i * 256;
        v[i] = p[c] * 0.03125f - 1e9f * mp[c];
        mx = fmaxf(mx, v[i]);
    }
    __shared__ float red[8];
#pragma unroll
    for (int o = 16; o; o >>= 1) mx = fmaxf(mx, __shfl_xor_sync(0xffffffffu, mx, o));
    if ((tid & 31) == 0) red[tid >> 5] = mx;
    __syncthreads();
    mx = red[0];
#pragma unroll
    for (int w = 1; w < 8; w++) mx = fmaxf(mx, red[w]);
    __syncthreads();

    float s = 0.0f;
#pragma unroll
    for (int i = 0; i < 4; i++) {
        v[i] = expf(v[i] - mx);
        s += v[i];
    }
#pragma unroll
    for (int o = 16; o; o >>= 1) s += __shfl_xor_sync(0xffffffffu, s, o);
    if ((tid & 31) == 0) red[tid >> 5] = s;
    __syncthreads();
    s = red[0];
#pragma unroll
    for (int w = 1; w < 8; w++) s += red[w];
    const float inv = 1.0f / s;
#pragma unroll
    for (int i = 0; i < 4; i++) {
        const int c = tid + i * 256;
        const float r = v[i] * inv;
        p[c] = r;
        ph[c] = __float2half_rn(r);
    }
}

// ---------------------------------------------------------------------------
extern "C" void kernel_launch(void* const* d_in, const int* in_sizes, int n_in,
                              void* d_out, int out_size)
{
    const float* x    = (const float*)d_in[0];
    const float* mask = (const float*)d_in[1];
    const float* Wq   = (const float*)d_in[2];
    const float* Wk   = (const float*)d_in[3];
    const float* Wv   = (const float*)d_in[4];
    const float* Wo   = (const float*)d_in[5];
    float* out  = (float*)d_out;
    float* attn = out + 4LL * 1024 * 1024;

    __half *xh, *wkh, *wqT, *wvT, *wog, *Gh, *Uh, *Ph, *Yh, *ah;
    cudaGetSymbolAddress((void**)&xh,  h_x);
    cudaGetSymbolAddress((void**)&wkh, h_wk);
    cudaGetSymbolAddress((void**)&wqT, h_wqT);
    cudaGetSymbolAddress((void**)&wvT, h_wvT);
    cudaGetSymbolAddress((void**)&wog, h_wog);
    cudaGetSymbolAddress((void**)&Gh,  h_G);
    cudaGetSymbolAddress((void**)&Uh,  h_U);
    cudaGetSymbolAddress((void**)&Ph,  h_P);
    cudaGetSymbolAddress((void**)&Yh,  h_Y);
    cudaGetSymbolAddress((void**)&ah,  h_attn);

    cudaFuncSetAttribute((const void*)gemm_h<false, false, 0, true>,
                         cudaFuncAttributeMaxDynamicSharedMemorySize, SMEM_BYTES);
    cudaFuncSetAttribute((const void*)gemm_h<true, false, 1, false>,
                         cudaFuncAttributeMaxDynamicSharedMemorySize, SMEM_BYTES);
    cudaFuncSetAttribute((const void*)gemm_h<false, true, 0, false>,
                         cudaFuncAttributeMaxDynamicSharedMemorySize, SMEM_BYTES);

    const long long M1 = 1024LL * 1024;
    const long long M4 = 4096LL * 1024;
    const dim3 blk(256);

    // 0) conversions / layout prep
    f2h_kernel<<<4096, 256>>>((const float4*)x, (__half2*)xh);
    f2h_kernel<<<16384, 256>>>((const float4*)Wk, (__half2*)wkh);
    f2h_T<<<dim3(32, 32, 16), dim3(32, 8)>>>(Wq, wqT);
    f2h_T<<<dim3(32, 32, 16), dim3(32, 8)>>>(Wv, wvT);
    f2h_gather<<<16384, 256>>>((const float4*)Wo, (__half2*)wog);

    // 1) G_h = Wq_h^T @ Wk_h  (NN, M=N=K=1024, 16 heads), half out
    const dim3 g16(8, 8, 16);
    gemm_h<false, false, 0, true><<<g16, blk, SMEM_BYTES>>>(
        wqT, wkh, Gh, 1024, 1024, 1024, M1, M1, M1, 1024, 1, 1);

    // 2) U_h = Wv_h^T @ Wo'_h  (NN), half out
    gemm_h<false, false, 0, true><<<g16, blk, SMEM_BYTES>>>(
        wvT, wog, Uh, 1024, 1024, 1024, M1, M1, M1, 1024, 1, 1);

    // 3) P = x @ G_h  (NN, M=4096 per head), half out
    const dim3 gp(8, 32, 16);
    gemm_h<false, false, 0, true><<<gp, blk, SMEM_BYTES>>>(
        xh, Gh, Ph, 1024, 1024, 1024, 0, M1, M4, 1024, 0, 1);

    // 4) logits = P_{h,b} @ x_b^T  (BT, z=h*4+b), fp32 store at [b,h]
    const dim3 gl(8, 8, 64);
    gemm_h<true, false, 1, false><<<gl, blk, SMEM_BYTES>>>(
        Ph, xh, attn, 1024, 1024, 1024, M1, M1, M1, 1024, 1, 2);

    // 5) masked softmax in place (scale 1/32) + half copy
    softmax_kernel<<<65536, 256>>>(attn, ah, mask);

    // 6) Y_{h,b} = x_b @ U_h  (NN, z=h*4+b), half out
    gemm_h<false, false, 0, true><<<gl, blk, SMEM_BYTES>>>(
        xh, Uh, Yh, 1024, 1024, 1024, M1, M1, M1, 1024, 2, 3);

    // 7) out_b = [attn_{:,b}] @ [Y_{:,b}]  (segmented K=16384, z=b), fp32
    const dim3 gf(8, 8, 4);
    gemm_h<false, true, 0, false><<<gf, blk, SMEM_BYTES>>>(
        ah, Yh, out, 1024, 1024, 1024, 16LL * M1, M1, M1, 16384, 1, 1);
}

// round 8
// speedup vs baseline: 7.7058x; 1.0337x over previous
#include <cuda_runtime.h>
#include <cstdint>
#include <cuda_fp16.h>
#include <mma.h>

using namespace nvcuda;

// Problem constants: B=4, L=1024, D=1024, H=16
// Half scratch buffers.
__device__ __half h_x[4194304];      // x [4096,1024]
__device__ __half h_wk[16777216];    // Wk [16,1024,1024]
__device__ __half h_wqT[16777216];   // Wq^T per head [16][i][d]
__device__ __half h_wvT[16777216];   // Wv^T per head [16][e][d]
__device__ __half h_wog[16777216];   // gathered Wo: [16][d][o]
__device__ __half h_G[16777216];     // G_h = Wq_h^T Wk_h
__device__ __half h_U[16777216];     // U_h = Wv_h^T Wo'_h
__device__ __half h_P[67108864];     // P = x @ G ; later reused as float[4][4M] split-K partials
__device__ __half h_Y[67108864];     // Y = x_b @ U_h  [(h*4+b)][1024][1024]
__device__ __half h_attn[67108864];  // attn half copy [(b*16+h)][1024][1024]

// ---------------------------------------------------------------------------
constexpr int BM = 128, BN = 128, BK = 64;
constexpr int STG = 3;
constexpr int LDA_S = BK + 8;            // 72 halves
constexpr int LDB_S = BN + 8;            // 136 halves
constexpr int A_TILE = BM * LDA_S;
constexpr int BT_TILE = BN * LDA_S;
constexpr int STAGE_H = A_TILE + BT_TILE;           // 18432 halves
constexpr int SMEM_BYTES = STG * STAGE_H * 2;       // 110592 B

__device__ __forceinline__ void cp16(const void* smem_dst, const void* src) {
    unsigned dst = (unsigned)__cvta_generic_to_shared(smem_dst);
    asm volatile("cp.async.cg.shared.global [%0], [%1], 16;\n" :: "r"(dst), "l"(src));
}
#define CP_COMMIT() asm volatile("cp.async.commit_group;" ::: "memory")
#define CP_WAIT(n)  asm volatile("cp.async.wait_group %0;" :: "n"(n) : "memory")

__device__ __forceinline__ int zmap(int z, int mode) {
    // 0 -> 0 ; 1 -> z ; 2 -> z&3 ; 3 -> z>>2 ; 4 -> zp
    switch (mode) {
        case 0: return 0;
        case 1: return z;
        case 2: return z & 3;
        case 3: return z >> 2;
        default: return (z & 3) * 16 + (z >> 2);
    }
}

// ---------------------------------------------------------------------------
// fp16 wmma GEMM, fp32 accumulate.
//   BT   : C = A @ B^T (B stored [N,K]); else C = A @ B (B stored [K,N]).
//   SEGK : segmented-K (local K split into 1024-row head segments):
//          A tile base = A + (k0>>10)<<20 + (k0&1023), row stride 1024
//          B tile base = B + (k0>>10)<<22 + (k0&1023)*1024, row stride 1024
//   CMODE: 0 -> C + z*sC;  1 -> C + zp*sC (fp32 only).
//   HOUT : half output via smem staging; else direct fp32 wmma store.
//   sA2/sB2: extra batch offset applied with factor (z>>2) (0 when unused).
// ---------------------------------------------------------------------------
template <bool BT, bool SEGK, int CMODE, bool HOUT>
__global__ __launch_bounds__(256, 2) void gemm_h(
    const __half* __restrict__ Ag, const __half* __restrict__ Bg, void* __restrict__ Cg,
    int lda, int ldb, int ldc,
    long long sA, long long sB, long long sC,
    long long sA2, long long sB2,
    int K, int aZ, int bZ)
{
    const int z  = blockIdx.z;
    const int zp = (z & 3) * 16 + (z >> 2);
    const __half* A  = Ag + (long long)zmap(z, aZ) * sA + (long long)(z >> 2) * sA2;
    const __half* Bp = Bg + (long long)zmap(z, bZ) * sB + (long long)(z >> 2) * sB2;

    extern __shared__ __half smem[];
    __half* Asm = smem;
    __half* Bsm = smem + STG * A_TILE;

    const int tid = threadIdx.x;
    const int warpId = tid >> 5;
    const int lane = tid & 31;
    const int rowBase = blockIdx.y * BM;
    const int colBase = blockIdx.x * BN;
    const int wRow = (warpId >> 2) * 64;
    const int wCol = (warpId & 3) * 32;

    wmma::fragment<wmma::accumulator, 16, 16, 16, float> acc[4][2];
#pragma unroll
    for (int i = 0; i < 4; i++)
#pragma unroll
        for (int j = 0; j < 2; j++) wmma::fill_fragment(acc[i][j], 0.0f);

    const int T = K >> 6;

    auto issue = [&](int kt) {
        const int buf = kt % STG;
        const int k0 = kt << 6;
        const __half* At;
        const __half* Bt;
        int rs_a = lda, rs_b = ldb;
        if constexpr (SEGK) {
            const int hseg = k0 >> 10;
            const int m0 = k0 & 1023;
            At = A + ((long long)hseg << 20) + m0;
            Bt = Bp + ((long long)hseg << 22) + (long long)m0 * 1024;
            rs_a = 1024; rs_b = 1024;
        } else {
            At = A + k0;
            Bt = Bp + (BT ? k0 : (long long)k0 * ldb);
        }
#pragma unroll
        for (int i = 0; i < 4; i++) {
            const int c = tid + i * 256;
            const int r = c >> 3;
            const int col = (c & 7) << 3;
            cp16(&Asm[(buf * BM + r) * LDA_S + col],
                 &At[(long long)(rowBase + r) * rs_a + col]);
        }
        if constexpr (BT) {
#pragma unroll
            for (int i = 0; i < 4; i++) {
                const int c = tid + i * 256;
                const int r = c >> 3;
                const int col = (c & 7) << 3;
                cp16(&Bsm[(buf * BN + r) * LDA_S + col],
                     &Bt[(long long)(colBase + r) * rs_b + col]);
            }
        } else {
#pragma unroll
            for (int i = 0; i < 4; i++) {
                const int c = tid + i * 256;
                const int r = c >> 4;
                const int col = (c & 15) << 3;
                cp16(&Bsm[(buf * BK + r) * LDB_S + col],
                     &Bt[(long long)r * rs_b + colBase + col]);
            }
        }
    };

#pragma unroll
    for (int s = 0; s < STG - 1; s++) { issue(s); CP_COMMIT(); }

    for (int kt = 0; kt < T; kt++) {
        // One barrier per tile: after wait+barrier, (a) everyone's tile-kt copies
        // are visible, (b) all warps finished compute(kt-1), so overwriting
        // stage (kt-1)%STG via issue(kt+STG-1) is safe.
        CP_WAIT(STG - 2);
        __syncthreads();
        const int pf = kt + STG - 1;
        if (pf < T) issue(pf);
        CP_COMMIT();

        const int buf = kt % STG;
        const __half* Ab = &Asm[buf * BM * LDA_S];
        const __half* Bb = BT ? &Bsm[buf * BN * LDA_S] : &Bsm[buf * BK * LDB_S];

#pragma unroll
        for (int kk = 0; kk < BK; kk += 16) {
            wmma::fragment<wmma::matrix_a, 16, 16, 16, __half, wmma::row_major> af[4];
#pragma unroll
            for (int i = 0; i < 4; i++)
                wmma::load_matrix_sync(af[i], &Ab[(wRow + i * 16) * LDA_S + kk], LDA_S);
            if constexpr (BT) {
                wmma::fragment<wmma::matrix_b, 16, 16, 16, __half, wmma::col_major> bf[2];
#pragma unroll
                for (int j = 0; j < 2; j++)
                    wmma::load_matrix_sync(bf[j], &Bb[(wCol + j * 16) * LDA_S + kk], LDA_S);
#pragma unroll
                for (int i = 0; i < 4; i++)
#pragma unroll
                    for (int j = 0; j < 2; j++)
                        wmma::mma_sync(acc[i][j], af[i], bf[j], acc[i][j]);
            } else {
                wmma::fragment<wmma::matrix_b, 16, 16, 16, __half, wmma::row_major> bf[2];
#pragma unroll
                for (int j = 0; j < 2; j++)
                    wmma::load_matrix_sync(bf[j], &Bb[kk * LDB_S + wCol + j * 16], LDB_S);
#pragma unroll
                for (int i = 0; i < 4; i++)
#pragma unroll
                    for (int j = 0; j < 2; j++)
                        wmma::mma_sync(acc[i][j], af[i], bf[j], acc[i][j]);
            }
        }
    }

    if constexpr (!HOUT) {
        float* C = (float*)Cg + (long long)(CMODE == 1 ? zp : z) * sC;
#pragma unroll
        for (int i = 0; i < 4; i++)
#pragma unroll
            for (int j = 0; j < 2; j++) {
                float* cp = &C[(long long)(rowBase + wRow + i * 16) * ldc + colBase + wCol + j * 16];
                wmma::store_matrix_sync(cp, acc[i][j], ldc, wmma::mem_row_major);
            }
    } else {
        __syncthreads();
        float* patch = (float*)smem + warpId * 320;     // 16 x 20
        const int pr = lane & 15;
        const int ps = (lane >> 4) << 3;
#pragma unroll
        for (int i = 0; i < 4; i++)
#pragma unroll
            for (int j = 0; j < 2; j++) {
                wmma::store_matrix_sync(patch, acc[i][j], 20, wmma::mem_row_major);
                __syncwarp();
                union { uint4 u; __half2 hh[4]; } pk;
#pragma unroll
                for (int t = 0; t < 4; t++)
                    pk.hh[t] = __floats2half2_rn(patch[pr * 20 + ps + t * 2],
                                                 patch[pr * 20 + ps + t * 2 + 1]);
                const int row = rowBase + wRow + i * 16 + pr;
                const int col = colBase + wCol + j * 16;
                __half* dst = (__half*)Cg + (long long)z * sC + (long long)row * ldc + col + ps;
                *reinterpret_cast<uint4*>(dst) = pk.u;
                __syncwarp();
            }
    }
}

// ---------------------------------------------------------------------------
// Fused prep: one launch, 5 segments.
//   blocks [0, 4096)          : x -> xh (float4 copy-convert)
//   blocks [4096, 20480)      : Wk -> wkh
//   blocks [20480, 36864)     : Wq -> wqT (32x32 transpose tiles)
//   blocks [36864, 53248)     : Wv -> wvT
//   blocks [53248, 69632)     : Wo gather -> wog
// ---------------------------------------------------------------------------
__global__ __launch_bounds__(256) void prep_kernel(
    const float* __restrict__ x,  const float* __restrict__ Wq,
    const float* __restrict__ Wk, const float* __restrict__ Wv,
    const float* __restrict__ Wo,
    __half* __restrict__ xh, __half* __restrict__ wqT,
    __half* __restrict__ wkh, __half* __restrict__ wvT,
    __half* __restrict__ wog)
{
    const int blk = blockIdx.x;
    const int t = threadIdx.x;

    if (blk < 20480) {
        // convert segments
        const float4* src; __half2* dst; int idx;
        if (blk < 4096) { src = (const float4*)x;  dst = (__half2*)xh;  idx = blk * 256 + t; }
        else            { src = (const float4*)Wk; dst = (__half2*)wkh; idx = (blk - 4096) * 256 + t; }
        const float4 v = src[idx];
        dst[2 * idx]     = __floats2half2_rn(v.x, v.y);
        dst[2 * idx + 1] = __floats2half2_rn(v.z, v.w);
    } else if (blk < 53248) {
        // per-head 32x32 transpose: tile index within 16384-block segment
        const float* src; __half* dst; int ti;
        if (blk < 36864) { src = Wq; dst = wqT; ti = blk - 20480; }
        else             { src = Wv; dst = wvT; ti = blk - 36864; }
        const int zh = ti >> 10;             // head
        const int by = ((ti >> 5) & 31) * 32; // d base
        const int bx = (ti & 31) * 32;        // i base
        const float* s = src + (long long)zh * 1048576;
        __half* d = dst + (long long)zh * 1048576;
        __shared__ float tt[32][33];
        const int tx = t & 31, ty = t >> 5;
#pragma unroll
        for (int i = 0; i < 4; i++)
            tt[ty + i * 8][tx] = s[(long long)(by + ty + i * 8) * 1024 + bx + tx];
        __syncthreads();
#pragma unroll
        for (int i = 0; i < 4; i++)
            d[(long long)(bx + ty + i * 8) * 1024 + by + tx] =
                __float2half_rn(tt[tx][ty + i * 8]);
    } else {
        // Wo gather: wog[h][dd][o] = Wo[((dd>>6)*16+h)*64+(dd&63)][o]
        const int idx = (blk - 53248) * 256 + t;   // < 16*1024*256
        const int o4 = idx & 255;
        const int dd = (idx >> 8) & 1023;
        const int h  = idx >> 18;
        const int srcRow = ((dd >> 6) * 16 + h) * 64 + (dd & 63);
        const float4 v = ((const float4*)Wo)[(long long)srcRow * 256 + o4];
        __half2* dst = (__half2*)wog;
        dst[2 * idx]     = __floats2half2_rn(v.x, v.y);
        dst[2 * idx + 1] = __floats2half2_rn(v.z, v.w);
    }
}

// ---------------------------------------------------------------------------
// In-place masked softmax; also emits half copy for the final GEMM.
// ---------------------------------------------------------------------------
__global__ __launch_bounds__(256) void softmax_kernel(
    float* __restrict__ attn, __half* __restrict__ attnh, const float* __restrict__ mask)
{
    const int row = blockIdx.x;          // 0 .. 65535
    const int b = row >> 14;
    const int l = row & 1023;
    float* p = attn + (long long)row * 1024;
    __half* ph = attnh + (long long)row * 1024;
    const float* mp = mask + ((long long)(b << 10) + l) * 1024;

    const int tid = threadIdx.x;
    float v[4];
    float mx = -3.4e38f;
#pragma unroll
    for (int i = 0; i < 4; i++) {
        const int c = tid + i * 256;
        v[i] = p[c] * 0.03125f - 1e9f * mp[c];
        mx = fmaxf(mx, v[i]);
    }
    __shared__ float red[8];
#pragma unroll
    for (int o = 16; o; o >>= 1) mx = fmaxf(mx, __shfl_xor_sync(0xffffffffu, mx, o));
    if ((tid & 31) == 0) red[tid >> 5] = mx;
    __syncthreads();
    mx = red[0];
#pragma unroll
    for (int w = 1; w < 8; w++) mx = fmaxf(mx, red[w]);
    __syncthreads();

    float s = 0.0f;
#pragma unroll
    for (int i = 0; i < 4; i++) {
        v[i] = __expf(v[i] - mx);
        s += v[i];
    }
#pragma unroll
    for (int o = 16; o; o >>= 1) s += __shfl_xor_sync(0xffffffffu, s, o);
    if ((tid & 31) == 0) red[tid >> 5] = s;
    __syncthreads();
    s = red[0];
#pragma unroll
    for (int w = 1; w < 8; w++) s += red[w];
    const float inv = 1.0f / s;
#pragma unroll
    for (int i = 0; i < 4; i++) {
        const int c = tid + i * 256;
        const float r = v[i] * inv;
        p[c] = r;
        ph[c] = __float2half_rn(r);
    }
}

// ---------------------------------------------------------------------------
// Split-K reduce: out[i] = sum of 4 partials (each 4M floats).
// ---------------------------------------------------------------------------
__global__ __launch_bounds__(256) void reduce4_kernel(
    const float4* __restrict__ part, float4* __restrict__ out)
{
    const int i = blockIdx.x * 256 + threadIdx.x;   // < 1M float4
    float4 a = part[i];
    const float4 b = part[i + 1048576];
    const float4 c = part[i + 2097152];
    const float4 d = part[i + 3145728];
    a.x += b.x + c.x + d.x;
    a.y += b.y + c.y + d.y;
    a.z += b.z + c.z + d.z;
    a.w += b.w + c.w + d.w;
    out[i] = a;
}

// ---------------------------------------------------------------------------
extern "C" void kernel_launch(void* const* d_in, const int* in_sizes, int n_in,
                              void* d_out, int out_size)
{
    const float* x    = (const float*)d_in[0];
    const float* mask = (const float*)d_in[1];
    const float* Wq   = (const float*)d_in[2];
    const float* Wk   = (const float*)d_in[3];
    const float* Wv   = (const float*)d_in[4];
    const float* Wo   = (const float*)d_in[5];
    float* out  = (float*)d_out;
    float* attn = out + 4LL * 1024 * 1024;

    __half *xh, *wkh, *wqT, *wvT, *wog, *Gh, *Uh, *Ph, *Yh, *ah;
    cudaGetSymbolAddress((void**)&xh,  h_x);
    cudaGetSymbolAddress((void**)&wkh, h_wk);
    cudaGetSymbolAddress((void**)&wqT, h_wqT);
    cudaGetSymbolAddress((void**)&wvT, h_wvT);
    cudaGetSymbolAddress((void**)&wog, h_wog);
    cudaGetSymbolAddress((void**)&Gh,  h_G);
    cudaGetSymbolAddress((void**)&Uh,  h_U);
    cudaGetSymbolAddress((void**)&Ph,  h_P);
    cudaGetSymbolAddress((void**)&Yh,  h_Y);
    cudaGetSymbolAddress((void**)&ah,  h_attn);
    float* partial = (float*)Ph;   // reuse h_P after logits GEMM (64 MB of 128 MB)

    cudaFuncSetAttribute((const void*)gemm_h<false, false, 0, true>,
                         cudaFuncAttributeMaxDynamicSharedMemorySize, SMEM_BYTES);
    cudaFuncSetAttribute((const void*)gemm_h<true, false, 1, false>,
                         cudaFuncAttributeMaxDynamicSharedMemorySize, SMEM_BYTES);
    cudaFuncSetAttribute((const void*)gemm_h<false, true, 0, false>,
                         cudaFuncAttributeMaxDynamicSharedMemorySize, SMEM_BYTES);

    const long long M1 = 1024LL * 1024;
    const long long M4 = 4096LL * 1024;
    const dim3 blk(256);

    // 0) fused prep (x, Wk convert; Wq, Wv transpose; Wo gather)
    prep_kernel<<<69632, 256>>>(x, Wq, Wk, Wv, Wo, xh, wqT, wkh, wvT, wog);

    // 1) G_h = Wq_h^T @ Wk_h  (NN, 16 heads), half out
    const dim3 g16(8, 8, 16);
    gemm_h<false, false, 0, true><<<g16, blk, SMEM_BYTES>>>(
        wqT, wkh, Gh, 1024, 1024, 1024, M1, M1, M1, 0, 0, 1024, 1, 1);

    // 2) U_h = Wv_h^T @ Wo'_h  (NN), half out
    gemm_h<false, false, 0, true><<<g16, blk, SMEM_BYTES>>>(
        wvT, wog, Uh, 1024, 1024, 1024, M1, M1, M1, 0, 0, 1024, 1, 1);

    // 3) P = x @ G_h  (NN, M=4096 per head), half out
    const dim3 gp(8, 32, 16);
    gemm_h<false, false, 0, true><<<gp, blk, SMEM_BYTES>>>(
        xh, Gh, Ph, 1024, 1024, 1024, 0, M1, M4, 0, 0, 1024, 0, 1);

    // 4) logits = P_{h,b} @ x_b^T  (BT, z=h*4+b), fp32 store at [b,h]
    const dim3 gl(8, 8, 64);
    gemm_h<true, false, 1, false><<<gl, blk, SMEM_BYTES>>>(
        Ph, xh, attn, 1024, 1024, 1024, M1, M1, M1, 0, 0, 1024, 1, 2);

    // 5) masked softmax in place (scale 1/32) + half copy
    softmax_kernel<<<65536, 256>>>(attn, ah, mask);

    // 6) Y_{h,b} = x_b @ U_h  (NN, z=h*4+b), half out
    gemm_h<false, false, 0, true><<<gl, blk, SMEM_BYTES>>>(
        xh, Uh, Yh, 1024, 1024, 1024, M1, M1, M1, 0, 0, 1024, 2, 3);

    // 7) split-K final: partial[c][b] = attn_{h in chunk c, b} @ Y_{...}
    //    z = c*4+b: A = ah + b*16M + c*4M; B = Yh + b*1M + c*16M; C = partial + z*1M
    const dim3 gf(8, 8, 16);
    gemm_h<false, true, 0, false><<<gf, blk, SMEM_BYTES>>>(
        ah, Yh, partial, 1024, 1024, 1024,
        16LL * M1, M1, M1, 4LL * M1, 16LL * M1, 4096, 2, 2);

    // 8) reduce partials -> out
    reduce4_kernel<<<4096, 256>>>((const float4*)partial, (float4*)out);
}